// round 9
// baseline (speedup 1.0000x reference)
#include <cuda_runtime.h>

#define FULL_MASK 0xffffffffu
#define DIM 768
#define NEXP 8
#define VEC (DIM / 4)          // 192 float4 per row
#define HVEC (VEC / 2)         // 96 float4 per half-row
#define ROWS_PER_BLOCK 32
#define STAGE_ROWS 4
#define NSTAGES (ROWS_PER_BLOCK / STAGE_ROWS)   // 8
#define DEPTH 3                                 // smem pipeline stages

__device__ __forceinline__ unsigned long long pack2(float a, float b) {
    unsigned long long p;
    asm("mov.b64 %0, {%1, %2};" : "=l"(p) : "f"(a), "f"(b));
    return p;
}
__device__ __forceinline__ void fma2(unsigned long long& acc,
                                     unsigned long long a,
                                     unsigned long long b) {
    asm("fma.rn.f32x2 %0, %1, %2, %0;" : "+l"(acc) : "l"(a), "l"(b));
}
__device__ __forceinline__ void unpack2(unsigned long long p, float& a, float& b) {
    asm("mov.b64 {%0, %1}, %2;" : "=f"(a), "=f"(b) : "l"(p));
}

__global__ __launch_bounds__(256, 2)
void router_kernel(const float* __restrict__ x,
                   const float* __restrict__ W,
                   const float* __restrict__ bias,
                   float* __restrict__ out,
                   int nrows) {
    // x staging: DEPTH stages x 4 rows x 768 floats = 36 KB
    __shared__ __align__(16) float xs[DEPTH][STAGE_ROWS * DIM];
    __shared__ float sh[ROWS_PER_BLOCK][2][NEXP];   // logits halves

    const int tid   = threadIdx.x;
    const int warp  = tid >> 5;
    const int lane  = tid & 31;
    const int slot  = warp >> 2;        // row slot 0..1 within a sub-iteration
    const int dhalf = (warp >> 1) & 1;  // dim half
    const int ehalf = warp & 1;         // expert half
    const int rowBase = blockIdx.x * ROWS_PER_BLOCK;
    const size_t totalFloats = (size_t)nrows * DIM;

    // ---- W slice in registers: 4 experts x 12 cols/lane (half-row) = 48 regs ----
    const float4* W4 = (const float4*)W;
    unsigned long long wpk[4][6];
    #pragma unroll
    for (int e = 0; e < 4; ++e) {
        #pragma unroll
        for (int c = 0; c < 3; ++c) {
            float4 w = __ldg(&W4[(ehalf * 4 + e) * VEC + dhalf * HVEC + lane + 32 * c]);
            wpk[e][2 * c]     = pack2(w.x, w.y);
            wpk[e][2 * c + 1] = pack2(w.z, w.w);
        }
    }

    // ---- cp.async stage issue: 4 rows (12 KB) = 768 x 16B, 3 chunks/thread ----
    auto issue_stage = [&](int g) {
        const size_t base = (size_t)(rowBase + g * STAGE_ROWS) * DIM;
        float* dst = &xs[g % DEPTH][tid * 4];
        #pragma unroll
        for (int c = 0; c < 3; ++c) {
            size_t fo = base + tid * 4 + 1024 * c;
            if (fo + 4 > totalFloats) fo = totalFloats - 4;   // tail clamp (harmless dup)
            unsigned saddr = (unsigned)__cvta_generic_to_shared(dst + 1024 * c);
            asm volatile("cp.async.cg.shared.global [%0], [%1], 16;"
                         :: "r"(saddr), "l"(x + fo));
        }
        asm volatile("cp.async.commit_group;" ::: "memory");
    };

    issue_stage(0);
    issue_stage(1);

    for (int g = 0; g < NSTAGES; ++g) {
        // Drain fix: on the last stage no further commits follow, so "allow 1
        // pending" would skip waiting for THIS stage. Wait for everything.
        if (g == NSTAGES - 1)
            asm volatile("cp.async.wait_group 0;" ::: "memory");
        else
            asm volatile("cp.async.wait_group 1;" ::: "memory");
        __syncthreads();                       // stage g visible to all warps

        // Early issue: after the barrier above, every warp has finished reading
        // buffer (g-1)%DEPTH (its stage g-1 reads preceded iter g-1's barrier),
        // so stage g+2 can start filling it while we compute stage g.
        if (g + 2 < NSTAGES) issue_stage(g + 2);

        const float* stagep = xs[g % DEPTH];
        #pragma unroll
        for (int sub = 0; sub < 2; ++sub) {
            const int rowin = sub * 2 + slot;  // 0..3 within stage
            const float4* xsrc =
                (const float4*)(stagep + rowin * DIM + dhalf * (DIM / 2)) + lane;

            float4 xv0 = xsrc[0];
            float4 xv1 = xsrc[32];
            float4 xv2 = xsrc[64];

            unsigned long long xp[6];
            xp[0] = pack2(xv0.x, xv0.y);  xp[1] = pack2(xv0.z, xv0.w);
            xp[2] = pack2(xv1.x, xv1.y);  xp[3] = pack2(xv1.z, xv1.w);
            xp[4] = pack2(xv2.x, xv2.y);  xp[5] = pack2(xv2.z, xv2.w);

            // 24 packed FMAs: 4 experts x 6 f32x2 pairs
            unsigned long long acc2[4] = {0ull, 0ull, 0ull, 0ull};
            #pragma unroll
            for (int j = 0; j < 6; ++j) {
                #pragma unroll
                for (int e = 0; e < 4; ++e) fma2(acc2[e], xp[j], wpk[e][j]);
            }

            float acc[4];
            #pragma unroll
            for (int e = 0; e < 4; ++e) {
                float lo, hi;
                unpack2(acc2[e], lo, hi);
                acc[e] = lo + hi;
            }

            // Warp reduce 4 values in 12 SHFL
            #pragma unroll
            for (int e = 0; e < 4; ++e)
                acc[e] += __shfl_xor_sync(FULL_MASK, acc[e], 16);
            float b0 = (lane < 16) ? acc[0] : acc[2];
            float b1 = (lane < 16) ? acc[1] : acc[3];
            #pragma unroll
            for (int off = 8; off; off >>= 1) {
                b0 += __shfl_xor_sync(FULL_MASK, b0, off);
                b1 += __shfl_xor_sync(FULL_MASK, b1, off);
            }

            if ((lane & 15) == 0) {
                int r = g * STAGE_ROWS + rowin;
                int ebase = ehalf * 4 + (lane >> 4) * 2;
                sh[r][dhalf][ebase]     = b0;
                sh[r][dhalf][ebase + 1] = b1;
            }
        }
    }

    __syncthreads();   // sh complete before epilogue

    // ---- Epilogue: one thread per row -> combine halves + bias + softmax + top-2 ----
    if (tid < ROWS_PER_BLOCK) {
        int row = rowBase + tid;
        if (row < nrows) {
            float l[NEXP];
            #pragma unroll
            for (int e = 0; e < NEXP; ++e)
                l[e] = sh[tid][0][e] + sh[tid][1][e] + __ldg(&bias[e]);

            // top-1 / top-2 (first occurrence on ties, matching jax.lax.top_k)
            int i1 = 0; float v1 = l[0];
            #pragma unroll
            for (int e = 1; e < NEXP; ++e)
                if (l[e] > v1) { v1 = l[e]; i1 = e; }
            int i2 = -1; float v2 = -3.0e38f;
            #pragma unroll
            for (int e = 0; e < NEXP; ++e)
                if (e != i1 && l[e] > v2) { v2 = l[e]; i2 = e; }

            float s = 0.0f;
            #pragma unroll
            for (int e = 0; e < NEXP; ++e) s += expf(l[e] - v1);
            float inv = 1.0f / s;
            float g1 = inv;                   // expf(v1 - v1) = 1
            float g2 = expf(v2 - v1) * inv;

            // Output: gates [nrows,2] first, then indices [nrows,2] as floats
            out[(size_t)row * 2]     = g1;
            out[(size_t)row * 2 + 1] = g2;
            float* oi = out + (size_t)nrows * 2;
            oi[(size_t)row * 2]     = (float)i1;
            oi[(size_t)row * 2 + 1] = (float)i2;
        }
    }
}

extern "C" void kernel_launch(void* const* d_in, const int* in_sizes, int n_in,
                              void* d_out, int out_size) {
    const float* x = (const float*)d_in[0];   // [128,197,768] fp32
    const float* W = (const float*)d_in[1];   // [8,768] fp32
    const float* b = (const float*)d_in[2];   // [8] fp32
    float* out = (float*)d_out;

    int nrows = in_sizes[0] / DIM;            // 128*197 = 25216
    int grid = (nrows + ROWS_PER_BLOCK - 1) / ROWS_PER_BLOCK;

    router_kernel<<<grid, 256>>>(x, W, b, out, nrows);
}

// round 10
// speedup vs baseline: 1.7590x; 1.7590x over previous
#include <cuda_runtime.h>

#define FULL_MASK 0xffffffffu
#define DIM 768
#define NEXP 8
#define ROWU64 (DIM / 2)       // 384 u64 (float2 pairs) per row
#define HU64 (ROWU64 / 2)      // 192 u64 per half-row
#define ROWS_PER_BLOCK 32
#define ITERS 16               // 16 iterations x 2 row-slots = 32 rows
#define DEPTH 3                // per-warp register pipeline depth

typedef unsigned long long u64;

__device__ __forceinline__ void fma2(u64& acc, u64 a, u64 b) {
    asm("fma.rn.f32x2 %0, %1, %2, %0;" : "+l"(acc) : "l"(a), "l"(b));
}
__device__ __forceinline__ void unpack2(u64 p, float& a, float& b) {
    asm("mov.b64 {%0, %1}, %2;" : "=f"(a), "=f"(b) : "l"(p));
}

__global__ __launch_bounds__(256, 2)
void router_kernel(const float* __restrict__ x,
                   const float* __restrict__ W,
                   const float* __restrict__ bias,
                   float* __restrict__ out,
                   int nrows) {
    __shared__ float sh[ROWS_PER_BLOCK][2][NEXP];   // logits halves

    const int tid   = threadIdx.x;
    const int warp  = tid >> 5;
    const int lane  = tid & 31;
    const int slot  = warp >> 2;        // row slot 0..1 within an iteration
    const int dhalf = (warp >> 1) & 1;  // dim half: cols [0,384) or [384,768)
    const int ehalf = warp & 1;         // expert half: e0..3 or e4..7
    const int rowBase = blockIdx.x * ROWS_PER_BLOCK;

    // ---- W slice in registers: 4 experts x 6 u64 (12 cols)/lane = 48 regs.
    //      Loaded directly as u64 (float2 memory layout == f32x2 operand). ----
    const u64* Wu = (const u64*)W;
    u64 wpk[4][6];
    #pragma unroll
    for (int e = 0; e < 4; ++e) {
        #pragma unroll
        for (int c = 0; c < 6; ++c)
            wpk[e][c] = __ldg(&Wu[(ehalf * 4 + e) * ROWU64 + dhalf * HU64 + lane + 32 * c]);
    }

    const u64* xu = (const u64*)x + dhalf * HU64 + lane;

    // ---- Depth-3 per-warp register pipeline (no barriers in main loop) ----
    u64 xbuf[DEPTH][6];
    #pragma unroll
    for (int p = 0; p < DEPTH; ++p) {
        int row = rowBase + p * 2 + slot;
        if (row >= nrows) row = nrows - 1;           // clamp (nrows%32==0 normally)
        const u64* src = xu + (size_t)row * ROWU64;
        #pragma unroll
        for (int c = 0; c < 6; ++c) xbuf[p][c] = __ldg(&src[32 * c]);
    }

    #pragma unroll
    for (int i = 0; i < ITERS; ++i) {
        const int b = i % DEPTH;

        // 24 packed FMAs: 4 experts x 6 f32x2 pairs (consumes xbuf[b])
        u64 acc2[4] = {0ull, 0ull, 0ull, 0ull};
        #pragma unroll
        for (int j = 0; j < 6; ++j) {
            #pragma unroll
            for (int e = 0; e < 4; ++e) fma2(acc2[e], xbuf[b][j], wpk[e][j]);
        }

        // Refill the consumed buffer with row i+DEPTH (2 buffers stay in flight)
        if (i + DEPTH < ITERS) {
            int row = rowBase + (i + DEPTH) * 2 + slot;
            if (row >= nrows) row = nrows - 1;
            const u64* src = xu + (size_t)row * ROWU64;
            #pragma unroll
            for (int c = 0; c < 6; ++c) xbuf[b][c] = __ldg(&src[32 * c]);
        }

        float acc[4];
        #pragma unroll
        for (int e = 0; e < 4; ++e) {
            float lo, hi;
            unpack2(acc2[e], lo, hi);
            acc[e] = lo + hi;
        }

        // Warp reduce 4 values in 12 SHFL
        #pragma unroll
        for (int e = 0; e < 4; ++e)
            acc[e] += __shfl_xor_sync(FULL_MASK, acc[e], 16);
        float b0 = (lane < 16) ? acc[0] : acc[2];
        float b1 = (lane < 16) ? acc[1] : acc[3];
        #pragma unroll
        for (int off = 8; off; off >>= 1) {
            b0 += __shfl_xor_sync(FULL_MASK, b0, off);
            b1 += __shfl_xor_sync(FULL_MASK, b1, off);
        }

        if ((lane & 15) == 0) {
            int r = i * 2 + slot;
            int ebase = ehalf * 4 + (lane >> 4) * 2;
            sh[r][dhalf][ebase]     = b0;
            sh[r][dhalf][ebase + 1] = b1;
        }
    }

    __syncthreads();   // sh complete before epilogue

    // ---- Epilogue: one thread per row -> combine halves + bias + softmax + top-2 ----
    if (tid < ROWS_PER_BLOCK) {
        int row = rowBase + tid;
        if (row < nrows) {
            float l[NEXP];
            #pragma unroll
            for (int e = 0; e < NEXP; ++e)
                l[e] = sh[tid][0][e] + sh[tid][1][e] + __ldg(&bias[e]);

            // top-1 / top-2 (first occurrence on ties, matching jax.lax.top_k)
            int i1 = 0; float v1 = l[0];
            #pragma unroll
            for (int e = 1; e < NEXP; ++e)
                if (l[e] > v1) { v1 = l[e]; i1 = e; }
            int i2 = -1; float v2 = -3.0e38f;
            #pragma unroll
            for (int e = 0; e < NEXP; ++e)
                if (e != i1 && l[e] > v2) { v2 = l[e]; i2 = e; }

            float s = 0.0f;
            #pragma unroll
            for (int e = 0; e < NEXP; ++e) s += expf(l[e] - v1);
            float inv = 1.0f / s;
            float g1 = inv;                   // expf(v1 - v1) = 1
            float g2 = expf(v2 - v1) * inv;

            // Output: gates [nrows,2] first, then indices [nrows,2] as floats
            out[(size_t)row * 2]     = g1;
            out[(size_t)row * 2 + 1] = g2;
            float* oi = out + (size_t)nrows * 2;
            oi[(size_t)row * 2]     = (float)i1;
            oi[(size_t)row * 2 + 1] = (float)i2;
        }
    }
}

extern "C" void kernel_launch(void* const* d_in, const int* in_sizes, int n_in,
                              void* d_out, int out_size) {
    const float* x = (const float*)d_in[0];   // [128,197,768] fp32
    const float* W = (const float*)d_in[1];   // [8,768] fp32
    const float* b = (const float*)d_in[2];   // [8] fp32
    float* out = (float*)d_out;

    int nrows = in_sizes[0] / DIM;            // 128*197 = 25216
    int grid = (nrows + ROWS_PER_BLOCK - 1) / ROWS_PER_BLOCK;

    router_kernel<<<grid, 256>>>(x, W, b, out, nrows);
}